// round 4
// baseline (speedup 1.0000x reference)
#include <cuda_runtime.h>
#include <cstdint>

#define BB 32
#define TT 2048
#define FF 128
#define HH 512

// Scratch: precomputed input projection pre[b][t][h] = x W_ih^T + b_ih + b_hh
__device__ float g_pre[BB * TT * HH];   // 128 MiB
__device__ float g_v[HH];
__device__ float g_c;

// ---------------------------------------------------------------------------
// helpers
// ---------------------------------------------------------------------------
__device__ __forceinline__ uint32_t smem_u32(const void* p) {
    uint32_t a;
    asm("{ .reg .u64 t; cvta.to.shared.u64 t, %1; cvt.u32.u64 %0, t; }" : "=r"(a) : "l"(p));
    return a;
}
__device__ __forceinline__ uint32_t ctarank() {
    uint32_t r; asm("mov.u32 %0, %%cluster_ctarank;" : "=r"(r)); return r;
}
__device__ __forceinline__ uint32_t mapa_u32(uint32_t a, uint32_t r) {
    uint32_t o; asm("mapa.shared::cluster.u32 %0, %1, %2;" : "=r"(o) : "r"(a), "r"(r)); return o;
}
__device__ __forceinline__ void stc2(uint32_t a, float x, float y) {
    asm volatile("st.shared::cluster.v2.f32 [%0], {%1,%2};" :: "r"(a), "f"(x), "f"(y) : "memory");
}
__device__ __forceinline__ void cluster_sync_() {
    asm volatile("barrier.cluster.arrive.aligned;" ::: "memory");
    asm volatile("barrier.cluster.wait.aligned;" ::: "memory");
}
__device__ __forceinline__ void fma2(unsigned long long& acc, unsigned long long a,
                                     unsigned long long b) {
    asm("fma.rn.f32x2 %0, %1, %2, %0;" : "+l"(acc) : "l"(a), "l"(b));
}
__device__ __forceinline__ float hsum2(unsigned long long a) {
    float lo = __uint_as_float((unsigned)(a & 0xffffffffull));
    float hi = __uint_as_float((unsigned)(a >> 32));
    return lo + hi;
}
__device__ __forceinline__ float ftanh(float x) {
    // tanh(x) = 1 - 2/(e^{2x}+1); __expf handles +-inf gracefully. rel err ~1e-6.
    float e = __expf(2.0f * x);
    return 1.0f - __fdividef(2.0f, e + 1.0f);
}

// ---------------------------------------------------------------------------
// v = W2 @ W1 (R^512), c = b2 + W2.b1
// ---------------------------------------------------------------------------
__global__ void vc_kernel(const float* __restrict__ W1, const float* __restrict__ b1,
                          const float* __restrict__ W2, const float* __restrict__ b2) {
    __shared__ float w2s[FF];
    int tid = threadIdx.x;
    if (tid < FF) w2s[tid] = W2[tid];
    __syncthreads();
    if (tid < HH) {
        float s = 0.f;
#pragma unroll 16
        for (int f = 0; f < FF; ++f) s = fmaf(w2s[f], W1[f * HH + tid], s);
        g_v[tid] = s;
    }
    if (tid == 0) {
        float s = b2[0];
        for (int f = 0; f < FF; ++f) s = fmaf(w2s[f], b1[f], s);
        g_c = s;
    }
}

// ---------------------------------------------------------------------------
// Input projection GEMM: [B*T,128] @ [128,512]^T + bias -> g_pre.
// 64x64 tile per CTA, K-chunks of 32, transposed smem tiles.
// ---------------------------------------------------------------------------
__global__ void __launch_bounds__(256) pre_gemm(const float* __restrict__ x,
                                                const float* __restrict__ Wih,
                                                const float* __restrict__ bih,
                                                const float* __restrict__ bhh) {
    __shared__ float xsT[32][68];
    __shared__ float wsT[32][68];
    const int tid = threadIdx.x;
    const int tx = tid & 15, ty = tid >> 4;
    const int m0 = blockIdx.y << 6;
    const int n0 = blockIdx.x << 6;
    float acc[4][4] = {};
    for (int k0 = 0; k0 < FF; k0 += 32) {
#pragma unroll
        for (int i = 0; i < 8; ++i) {
            int e = (i << 8) + tid;
            int r = e >> 5, cc = e & 31;
            xsT[cc][r] = x[(size_t)(m0 + r) * FF + k0 + cc];
            wsT[cc][r] = Wih[(size_t)(n0 + r) * FF + k0 + cc];
        }
        __syncthreads();
#pragma unroll
        for (int kk = 0; kk < 32; ++kk) {
            float4 a = *(const float4*)&xsT[kk][ty << 2];
            float4 b = *(const float4*)&wsT[kk][tx << 2];
            acc[0][0] = fmaf(a.x, b.x, acc[0][0]); acc[0][1] = fmaf(a.x, b.y, acc[0][1]);
            acc[0][2] = fmaf(a.x, b.z, acc[0][2]); acc[0][3] = fmaf(a.x, b.w, acc[0][3]);
            acc[1][0] = fmaf(a.y, b.x, acc[1][0]); acc[1][1] = fmaf(a.y, b.y, acc[1][1]);
            acc[1][2] = fmaf(a.y, b.z, acc[1][2]); acc[1][3] = fmaf(a.y, b.w, acc[1][3]);
            acc[2][0] = fmaf(a.z, b.x, acc[2][0]); acc[2][1] = fmaf(a.z, b.y, acc[2][1]);
            acc[2][2] = fmaf(a.z, b.z, acc[2][2]); acc[2][3] = fmaf(a.z, b.w, acc[2][3]);
            acc[3][0] = fmaf(a.w, b.x, acc[3][0]); acc[3][1] = fmaf(a.w, b.y, acc[3][1]);
            acc[3][2] = fmaf(a.w, b.z, acc[3][2]); acc[3][3] = fmaf(a.w, b.w, acc[3][3]);
        }
        __syncthreads();
    }
    const int n = n0 + (tx << 2);
    float4 bias;
    bias.x = bih[n + 0] + bhh[n + 0];
    bias.y = bih[n + 1] + bhh[n + 1];
    bias.z = bih[n + 2] + bhh[n + 2];
    bias.w = bih[n + 3] + bhh[n + 3];
#pragma unroll
    for (int i = 0; i < 4; ++i) {
        int m = m0 + (ty << 2) + i;
        float4 o;
        o.x = acc[i][0] + bias.x;
        o.y = acc[i][1] + bias.y;
        o.z = acc[i][2] + bias.z;
        o.w = acc[i][3] + bias.w;
        *(float4*)&g_pre[(size_t)m * HH + n] = o;
    }
}

// ---------------------------------------------------------------------------
// Persistent recurrence: 16 clusters x 8 CTAs, cluster c owns batches 2c,2c+1.
// CTA rank r holds rows [64r,64r+64) of W_hh in registers (packed f32x2).
// Thread (g=tid>>3, s=tid&7): rows 64r+2g, 64r+2g+1; columns [64s,64s+64).
// Double-buffered h exchanged via DSMEM; one barrier.cluster per step.
// ---------------------------------------------------------------------------
__global__ void __launch_bounds__(256, 1) __cluster_dims__(8, 1, 1)
rnn_kernel(const int* __restrict__ lengths, const float* __restrict__ Whh,
           float* __restrict__ out, int out_size) {
    // padded layout: h index j lives at (j>>6)*68 + (j&63)  -> conflict-free LDS.128
    __shared__ __align__(16) float hbuf[2][2][544];   // [buf][batch][padded H]
    __shared__ float pdacc[2][2];                     // [buf][batch] partial dot accum
    __shared__ float pdall[2][8][2];                  // [buf][rank][batch] (read on rank 0)

    const int tid = threadIdx.x;
    const uint32_t rank = ctarank();
    const int cl = blockIdx.x >> 3;
    const int b0 = cl * 2, b1 = b0 + 1;
    const int len0 = lengths[b0], len1 = lengths[b1];
    const int tmax = (len0 > len1) ? len0 : len1;

    const int g = tid >> 3;
    const int s = tid & 7;
    const int rowA = (int)rank * 64 + 2 * g;    // two adjacent rows
    const int padA = (int)rank * 68 + 2 * g;    // padded position of rowA (rowB = +1)
    const int hoff = s * 68;                    // this thread's h slice (padded)

    // ---- load W_hh rows into registers as packed f32x2 pairs ----
    unsigned long long wA[32], wB[32];
    {
        const double2* pA = (const double2*)(Whh + (size_t)rowA * HH + s * 64);
        const double2* pB = (const double2*)(Whh + (size_t)(rowA + 1) * HH + s * 64);
#pragma unroll
        for (int i = 0; i < 16; ++i) {
            double2 a = pA[i], b = pB[i];
            wA[2 * i] = __double_as_longlong(a.x);
            wA[2 * i + 1] = __double_as_longlong(a.y);
            wB[2 * i] = __double_as_longlong(b.x);
            wB[2 * i + 1] = __double_as_longlong(b.y);
        }
    }

    // ---- init smem ----
    for (int i = tid; i < 1088; i += 256) (&hbuf[0][0][0])[i] = 0.f;  // hbuf[0]
    if (tid < 4) (&pdacc[0][0])[tid] = 0.f;

    const float vA = g_v[rowA];
    const float vB = g_v[rowA + 1];
    const float cval = g_c;

    // remote bases
    const uint32_t rbA = mapa_u32(smem_u32(&hbuf[0][0][0]), (uint32_t)s) + (uint32_t)padA * 4u;
    const uint32_t pdall_rm = mapa_u32(smem_u32(&pdall[0][0][0]), 0u) + rank * 8u;

    const float* pb0 = g_pre + (size_t)b0 * TT * HH;
    const float* pb1 = g_pre + (size_t)b1 * TT * HH;

    float hA0 = 0.f, hB0 = 0.f, hA1 = 0.f, hB1 = 0.f;
    int cnt0 = 0, cnt1 = 0;

    float2 pc0 = *(const float2*)(pb0 + rowA);   // pre for t=0
    float2 pc1 = *(const float2*)(pb1 + rowA);

    cluster_sync_();

    for (int t = 0; t < tmax + 2; ++t) {
        const int p = t & 1, q = p ^ 1;

        if (t < tmax) {
            // prefetch next pre
            const int tn = (t + 1 < tmax) ? (t + 1) : t;
            float2 pn0 = *(const float2*)(pb0 + (size_t)tn * HH + rowA);
            float2 pn1 = *(const float2*)(pb1 + (size_t)tn * HH + rowA);

            // register-resident matvec over this thread's 64-col slice
            const ulonglong2* h0 = (const ulonglong2*)&hbuf[p][0][hoff];
            const ulonglong2* h1 = (const ulonglong2*)&hbuf[p][1][hoff];
            unsigned long long aA0 = 0ull, aB0 = 0ull, aA1 = 0ull, aB1 = 0ull;
#pragma unroll
            for (int i = 0; i < 16; ++i) {
                ulonglong2 x0 = h0[i];
                ulonglong2 x1 = h1[i];
                fma2(aA0, wA[2 * i], x0.x); fma2(aA0, wA[2 * i + 1], x0.y);
                fma2(aB0, wB[2 * i], x0.x); fma2(aB0, wB[2 * i + 1], x0.y);
                fma2(aA1, wA[2 * i], x1.x); fma2(aA1, wA[2 * i + 1], x1.y);
                fma2(aB1, wB[2 * i], x1.x); fma2(aB1, wB[2 * i + 1], x1.y);
            }
            float sA0 = hsum2(aA0), sB0 = hsum2(aB0);
            float sA1 = hsum2(aA1), sB1 = hsum2(aB1);
#pragma unroll
            for (int m = 1; m < 8; m <<= 1) {
                sA0 += __shfl_xor_sync(0xffffffffu, sA0, m);
                sB0 += __shfl_xor_sync(0xffffffffu, sB0, m);
                sA1 += __shfl_xor_sync(0xffffffffu, sA1, m);
                sB1 += __shfl_xor_sync(0xffffffffu, sB1, m);
            }
            float nA0 = ftanh(pc0.x + sA0), nB0 = ftanh(pc0.y + sB0);
            float nA1 = ftanh(pc1.x + sA1), nB1 = ftanh(pc1.y + sB1);
            if (t < len0) { hA0 = nA0; hB0 = nB0; }
            if (t < len1) { hA1 = nA1; hB1 = nB1; }

            // publish both rows to peer s (lane s -> CTA s), buffer q
            stc2(rbA + (uint32_t)(q * 2 + 0) * 2176u, hA0, hB0);
            stc2(rbA + (uint32_t)(q * 2 + 1) * 2176u, hA1, hB1);

            // partial dot for the sign-count head (identical across s-group)
            float pd0 = fmaf(hA0, vA, hB0 * vB);
            float pd1 = fmaf(hA1, vA, hB1 * vB);
            pd0 += __shfl_xor_sync(0xffffffffu, pd0, 8);
            pd0 += __shfl_xor_sync(0xffffffffu, pd0, 16);
            pd1 += __shfl_xor_sync(0xffffffffu, pd1, 8);
            pd1 += __shfl_xor_sync(0xffffffffu, pd1, 16);
            if ((tid & 31) == 0) {
                atomicAdd(&pdacc[q][0], pd0);
                atomicAdd(&pdacc[q][1], pd1);
            }
            pc0 = pn0; pc1 = pn1;
        }

        // forward step (t-1)'s CTA-partial dot to rank 0
        if (t >= 1 && t <= tmax && tid == 0) {
            float f0 = pdacc[p][0], f1 = pdacc[p][1];
            pdacc[p][0] = 0.f; pdacc[p][1] = 0.f;
            stc2(pdall_rm + (uint32_t)p * 64u, f0, f1);
        }

        // rank 0: consume step (t-2)'s full dot, update counts
        if (t >= 2 && rank == 0 && tid < 16) {
            const int tc = t - 2;
            const int b = tid >> 3, l = tid & 7;
            float d = pdall[q][l][b];
            d += __shfl_xor_sync(0x0000ffffu, d, 1);
            d += __shfl_xor_sync(0x0000ffffu, d, 2);
            d += __shfl_xor_sync(0x0000ffffu, d, 4);
            if (l == 0) {
                float tot = d + cval;
                if (b == 0) { if (tot > 0.f && tc < len0) cnt0++; }
                else        { if (tot > 0.f && tc < len1) cnt1++; }
            }
        }

        cluster_sync_();
    }

    // ---- outputs: [counts (32)] then [h_final (32x512)] ----
    const int have_h = (out_size >= BB + BB * HH);
    if (rank == 0) {
        if (tid == 0) out[b0] = (float)cnt0;
        if (tid == 8) out[b1] = (float)cnt1;
    }
    if (have_h && tid < 128) {
        const int pf = tmax & 1;
        const int b = tid >> 6, j = tid & 63;
        out[BB + (size_t)(b0 + b) * HH + rank * 64 + j] = hbuf[pf][b][rank * 68 + j];
    }
}

// ---------------------------------------------------------------------------
// launch
// ---------------------------------------------------------------------------
extern "C" void kernel_launch(void* const* d_in, const int* in_sizes, int n_in,
                              void* d_out, int out_size) {
    const float* x    = (const float*)d_in[0];
    const int* lengths = (const int*)d_in[1];
    const float* W_ih = (const float*)d_in[2];
    const float* W_hh = (const float*)d_in[3];
    const float* b_ih = (const float*)d_in[4];
    const float* b_hh = (const float*)d_in[5];
    const float* W1   = (const float*)d_in[6];
    const float* b1   = (const float*)d_in[7];
    const float* W2   = (const float*)d_in[8];
    const float* b2   = (const float*)d_in[9];
    float* out = (float*)d_out;

    vc_kernel<<<1, 512>>>(W1, b1, W2, b2);

    dim3 ggrid(HH / 64, (BB * TT) / 64);   // (8, 1024)
    pre_gemm<<<ggrid, 256>>>(x, W_ih, b_ih, b_hh);

    rnn_kernel<<<128, 256>>>(lengths, W_hh, out, out_size);
}

// round 5
// speedup vs baseline: 1.4084x; 1.4084x over previous
#include <cuda_runtime.h>
#include <cstdint>

#define BB 32
#define TT 2048
#define FF 128
#define HH 512

// Scratch: precomputed input projection pre[b][t][h] = x W_ih^T + b_ih + b_hh
__device__ float g_pre[BB * TT * HH];   // 128 MiB
__device__ float g_v[HH];
__device__ float g_c;

// ---------------------------------------------------------------------------
// helpers
// ---------------------------------------------------------------------------
__device__ __forceinline__ uint32_t smem_u32(const void* p) {
    uint32_t a;
    asm("{ .reg .u64 t; cvta.to.shared.u64 t, %1; cvt.u32.u64 %0, t; }" : "=r"(a) : "l"(p));
    return a;
}
__device__ __forceinline__ uint32_t ctarank() {
    uint32_t r; asm("mov.u32 %0, %%cluster_ctarank;" : "=r"(r)); return r;
}
__device__ __forceinline__ uint32_t mapa_u32(uint32_t a, uint32_t r) {
    uint32_t o; asm("mapa.shared::cluster.u32 %0, %1, %2;" : "=r"(o) : "r"(a), "r"(r)); return o;
}
__device__ __forceinline__ void cluster_sync_() {
    asm volatile("barrier.cluster.arrive.aligned;" ::: "memory");
    asm volatile("barrier.cluster.wait.aligned;" ::: "memory");
}
__device__ __forceinline__ void fma2(unsigned long long& acc, unsigned long long a,
                                     unsigned long long b) {
    asm("fma.rn.f32x2 %0, %1, %2, %0;" : "+l"(acc) : "l"(a), "l"(b));
}
__device__ __forceinline__ float hsum2(unsigned long long a) {
    float lo = __uint_as_float((unsigned)(a & 0xffffffffull));
    float hi = __uint_as_float((unsigned)(a >> 32));
    return lo + hi;
}
__device__ __forceinline__ unsigned long long pk2(float lo, float hi) {
    return (unsigned long long)__float_as_uint(lo) |
           ((unsigned long long)__float_as_uint(hi) << 32);
}
__device__ __forceinline__ float ftanh(float x) {
    float e = __expf(2.0f * x);
    return 1.0f - __fdividef(2.0f, e + 1.0f);
}
// mbarrier ops
__device__ __forceinline__ void mbar_init(uint32_t a, uint32_t cnt) {
    asm volatile("mbarrier.init.shared.b64 [%0], %1;" :: "r"(a), "r"(cnt) : "memory");
}
__device__ __forceinline__ void mbar_arrive_expect(uint32_t a, uint32_t tx) {
    asm volatile("mbarrier.arrive.expect_tx.shared.b64 _, [%0], %1;" :: "r"(a), "r"(tx) : "memory");
}
__device__ __forceinline__ void mbar_wait(uint32_t a, uint32_t parity) {
    asm volatile(
        "{\n\t.reg .pred P;\n"
        "W_%=:\n\t"
        "mbarrier.try_wait.parity.acquire.cluster.shared::cta.b64 P, [%0], %1, 0x989680;\n\t"
        "@!P bra W_%=;\n\t"
        "}" :: "r"(a), "r"(parity) : "memory");
}
// remote DSMEM store with tx-counted completion on the peer's mbarrier
__device__ __forceinline__ void st_async64(uint32_t raddr, unsigned long long v, uint32_t rmbar) {
    asm volatile("st.async.shared::cluster.mbarrier::complete_tx::bytes.b64 [%0], %1, [%2];"
                 :: "r"(raddr), "l"(v), "r"(rmbar) : "memory");
}

// ---------------------------------------------------------------------------
// v = W2 @ W1 (R^512), c = b2 + W2.b1
// ---------------------------------------------------------------------------
__global__ void vc_kernel(const float* __restrict__ W1, const float* __restrict__ b1,
                          const float* __restrict__ W2, const float* __restrict__ b2) {
    __shared__ float w2s[FF];
    int tid = threadIdx.x;
    if (tid < FF) w2s[tid] = W2[tid];
    __syncthreads();
    if (tid < HH) {
        float s = 0.f;
#pragma unroll 16
        for (int f = 0; f < FF; ++f) s = fmaf(w2s[f], W1[f * HH + tid], s);
        g_v[tid] = s;
    }
    if (tid == 0) {
        float s = b2[0];
        for (int f = 0; f < FF; ++f) s = fmaf(w2s[f], b1[f], s);
        g_c = s;
    }
}

// ---------------------------------------------------------------------------
// Input projection GEMM: [B*T,128] @ [128,512]^T + bias -> g_pre.
// ---------------------------------------------------------------------------
__global__ void __launch_bounds__(256) pre_gemm(const float* __restrict__ x,
                                                const float* __restrict__ Wih,
                                                const float* __restrict__ bih,
                                                const float* __restrict__ bhh) {
    __shared__ float xsT[32][68];
    __shared__ float wsT[32][68];
    const int tid = threadIdx.x;
    const int tx = tid & 15, ty = tid >> 4;
    const int m0 = blockIdx.y << 6;
    const int n0 = blockIdx.x << 6;
    float acc[4][4] = {};
    for (int k0 = 0; k0 < FF; k0 += 32) {
#pragma unroll
        for (int i = 0; i < 8; ++i) {
            int e = (i << 8) + tid;
            int r = e >> 5, cc = e & 31;
            xsT[cc][r] = x[(size_t)(m0 + r) * FF + k0 + cc];
            wsT[cc][r] = Wih[(size_t)(n0 + r) * FF + k0 + cc];
        }
        __syncthreads();
#pragma unroll
        for (int kk = 0; kk < 32; ++kk) {
            float4 a = *(const float4*)&xsT[kk][ty << 2];
            float4 b = *(const float4*)&wsT[kk][tx << 2];
            acc[0][0] = fmaf(a.x, b.x, acc[0][0]); acc[0][1] = fmaf(a.x, b.y, acc[0][1]);
            acc[0][2] = fmaf(a.x, b.z, acc[0][2]); acc[0][3] = fmaf(a.x, b.w, acc[0][3]);
            acc[1][0] = fmaf(a.y, b.x, acc[1][0]); acc[1][1] = fmaf(a.y, b.y, acc[1][1]);
            acc[1][2] = fmaf(a.y, b.z, acc[1][2]); acc[1][3] = fmaf(a.y, b.w, acc[1][3]);
            acc[2][0] = fmaf(a.z, b.x, acc[2][0]); acc[2][1] = fmaf(a.z, b.y, acc[2][1]);
            acc[2][2] = fmaf(a.z, b.z, acc[2][2]); acc[2][3] = fmaf(a.z, b.w, acc[2][3]);
            acc[3][0] = fmaf(a.w, b.x, acc[3][0]); acc[3][1] = fmaf(a.w, b.y, acc[3][1]);
            acc[3][2] = fmaf(a.w, b.z, acc[3][2]); acc[3][3] = fmaf(a.w, b.w, acc[3][3]);
        }
        __syncthreads();
    }
    const int n = n0 + (tx << 2);
    float4 bias;
    bias.x = bih[n + 0] + bhh[n + 0];
    bias.y = bih[n + 1] + bhh[n + 1];
    bias.z = bih[n + 2] + bhh[n + 2];
    bias.w = bih[n + 3] + bhh[n + 3];
#pragma unroll
    for (int i = 0; i < 4; ++i) {
        int m = m0 + (ty << 2) + i;
        float4 o;
        o.x = acc[i][0] + bias.x;
        o.y = acc[i][1] + bias.y;
        o.z = acc[i][2] + bias.z;
        o.w = acc[i][3] + bias.w;
        *(float4*)&g_pre[(size_t)m * HH + n] = o;
    }
}

// ---------------------------------------------------------------------------
// Persistent recurrence: 16 clusters x 8 CTAs, cluster c owns batches 2c,2c+1.
// CTA rank r holds rows [64r,64r+64) of W_hh in registers (packed f32x2).
// NO cluster barrier in the loop: h is exchanged with st.async (tx-counted
// mbarriers, 4096 B expected per CTA per step), triple-buffered.
// rank 0 computes the sign-count head locally (it holds the full h).
// ---------------------------------------------------------------------------
#define BUF_F  1088          // floats per buffer (2 batches x 544 padded)
#define BUF_B  4352u         // bytes per buffer
#define BAT_B  2176u         // bytes per batch
#define EXPECT_TX 4096u      // bytes per CTA per step

__global__ void __launch_bounds__(256, 1) __cluster_dims__(8, 1, 1)
rnn_kernel(const int* __restrict__ lengths, const float* __restrict__ Whh,
           float* __restrict__ out, int out_size) {
    // padded layout: h index j lives at (j>>6)*68 + (j&63)
    __shared__ __align__(16) float hbuf[3][2][544];
    __shared__ __align__(8) unsigned long long mbar[3];

    const int tid = threadIdx.x;
    const int lane = tid & 31;
    const int wid = tid >> 5;
    const uint32_t rank = ctarank();
    const int cl = blockIdx.x >> 3;
    const int b0 = cl * 2, b1 = b0 + 1;
    const int len0 = lengths[b0], len1 = lengths[b1];
    const int tmax = (len0 > len1) ? len0 : len1;

    const int g = tid >> 3;
    const int s = tid & 7;
    const int rowA = (int)rank * 64 + 2 * g;
    const int padA = (int)rank * 68 + 2 * g;
    const int hoff = s * 68;

    // ---- W_hh rows -> registers (packed f32x2) ----
    unsigned long long wA[32], wB[32];
    {
        const double2* pA = (const double2*)(Whh + (size_t)rowA * HH + s * 64);
        const double2* pB = (const double2*)(Whh + (size_t)(rowA + 1) * HH + s * 64);
#pragma unroll
        for (int i = 0; i < 16; ++i) {
            double2 a = pA[i], b = pB[i];
            wA[2 * i]     = __double_as_longlong(a.x);
            wA[2 * i + 1] = __double_as_longlong(a.y);
            wB[2 * i]     = __double_as_longlong(b.x);
            wB[2 * i + 1] = __double_as_longlong(b.y);
        }
    }

    // ---- head vector for rank-0 count warps ----
    unsigned long long vv[8];
    float cval = 0.f;
    if (rank == 0 && wid < 2) {
#pragma unroll
        for (int c = 0; c < 8; ++c) {
            float2 t = *(const float2*)(g_v + c * 64 + 2 * lane);
            vv[c] = pk2(t.x, t.y);
        }
        cval = g_c;
    }

    // ---- init: zero buf 0, init mbarriers ----
    for (int i = tid; i < BUF_F; i += 256) (&hbuf[0][0][0])[i] = 0.f;
    const uint32_t mb_local = smem_u32(&mbar[0]);
    if (tid == 0) {
        mbar_init(mb_local + 0, 1);
        mbar_init(mb_local + 8, 1);
        mbar_init(mb_local + 16, 1);
    }
    __syncthreads();
    cluster_sync_();                     // mbarriers visible cluster-wide
    if (tid == 0) {                      // arm all three phases
        mbar_arrive_expect(mb_local + 0, EXPECT_TX);
        mbar_arrive_expect(mb_local + 8, EXPECT_TX);
        mbar_arrive_expect(mb_local + 16, EXPECT_TX);
    }

    // remote bases: peer s gets our rows at padA; peer s's mbarriers
    const uint32_t rb  = mapa_u32(smem_u32(&hbuf[0][0][0]), (uint32_t)s) + (uint32_t)padA * 4u;
    const uint32_t rmb = mapa_u32(mb_local, (uint32_t)s);

    const float* pb0 = g_pre + (size_t)b0 * TT * HH;
    const float* pb1 = g_pre + (size_t)b1 * TT * HH;

    float hA0 = 0.f, hB0 = 0.f, hA1 = 0.f, hB1 = 0.f;
    int cnt = 0;                 // warp0: batch0, warp1: batch1 (rank 0, lane 0)
    int par0 = 0, par1 = 0, par2 = 0;

    float2 pc0 = *(const float2*)(pb0 + rowA);
    float2 pc1 = *(const float2*)(pb1 + rowA);

    int p3 = 0;                          // t % 3
    for (int t = 0; t <= tmax; ++t) {
        const int q3 = (p3 == 2) ? 0 : p3 + 1;

        if (t > 0) {                     // consume writes from step t-1
            int par = (p3 == 0) ? par0 : (p3 == 1) ? par1 : par2;
            mbar_wait(mb_local + (uint32_t)p3 * 8u, (uint32_t)par);
            if (p3 == 0) par0 ^= 1; else if (p3 == 1) par1 ^= 1; else par2 ^= 1;
            if (tid == 0) mbar_arrive_expect(mb_local + (uint32_t)p3 * 8u, EXPECT_TX);
        }

        if (t < tmax) {
            const int tn = (t + 1 < tmax) ? (t + 1) : t;
            float2 pn0 = *(const float2*)(pb0 + (size_t)tn * HH + rowA);
            float2 pn1 = *(const float2*)(pb1 + (size_t)tn * HH + rowA);

            // register-resident matvec over this thread's 64-col slice
            const ulonglong2* h0 = (const ulonglong2*)&hbuf[p3][0][hoff];
            const ulonglong2* h1 = (const ulonglong2*)&hbuf[p3][1][hoff];
            unsigned long long aA0 = 0ull, aB0 = 0ull, aA1 = 0ull, aB1 = 0ull;
#pragma unroll
            for (int i = 0; i < 16; ++i) {
                ulonglong2 x0 = h0[i];
                ulonglong2 x1 = h1[i];
                fma2(aA0, wA[2 * i], x0.x); fma2(aA0, wA[2 * i + 1], x0.y);
                fma2(aB0, wB[2 * i], x0.x); fma2(aB0, wB[2 * i + 1], x0.y);
                fma2(aA1, wA[2 * i], x1.x); fma2(aA1, wA[2 * i + 1], x1.y);
                fma2(aB1, wB[2 * i], x1.x); fma2(aB1, wB[2 * i + 1], x1.y);
            }
            float sA0 = hsum2(aA0), sB0 = hsum2(aB0);
            float sA1 = hsum2(aA1), sB1 = hsum2(aB1);
#pragma unroll
            for (int m = 1; m < 8; m <<= 1) {
                sA0 += __shfl_xor_sync(0xffffffffu, sA0, m);
                sB0 += __shfl_xor_sync(0xffffffffu, sB0, m);
                sA1 += __shfl_xor_sync(0xffffffffu, sA1, m);
                sB1 += __shfl_xor_sync(0xffffffffu, sB1, m);
            }
            float nA0 = ftanh(pc0.x + sA0), nB0 = ftanh(pc0.y + sB0);
            float nA1 = ftanh(pc1.x + sA1), nB1 = ftanh(pc1.y + sB1);
            if (t < len0) { hA0 = nA0; hB0 = nB0; }
            if (t < len1) { hA1 = nA1; hB1 = nB1; }

            // publish both batches' row-pair to peer s, buffer q3 (+ tx signal)
            const uint32_t dst = rb + (uint32_t)q3 * BUF_B;
            const uint32_t dmb = rmb + (uint32_t)q3 * 8u;
            st_async64(dst,         pk2(hA0, hB0), dmb);
            st_async64(dst + BAT_B, pk2(hA1, hB1), dmb);

            pc0 = pn0; pc1 = pn1;
        }

        // rank 0, warps 0/1: sign-count head on h_state(t-1) = hbuf[p3]
        // (safe: buf p3 is not rewritten until step t+2, gated by our t+1 stores)
        if (rank == 0 && wid < 2 && t >= 1) {
            const int lenb = wid ? len1 : len0;
            const int tc = t - 1;
            if (tc < lenb) {
                const float* hb = &hbuf[p3][wid][0];
                unsigned long long acc = 0ull;
#pragma unroll
                for (int c = 0; c < 8; ++c) {
                    unsigned long long x = *(const unsigned long long*)(hb + c * 68 + 2 * lane);
                    fma2(acc, vv[c], x);
                }
                float d = hsum2(acc);
#pragma unroll
                for (int m = 1; m < 32; m <<= 1) d += __shfl_xor_sync(0xffffffffu, d, m);
                if (lane == 0 && d + cval > 0.f) cnt++;
            }
        }

        p3 = q3;
    }

    cluster_sync_();   // drain in-flight st.async before any CTA exits

    // ---- outputs: [counts (32)] then [h_final (32x512)] ----
    const int have_h = (out_size >= BB + BB * HH);
    if (rank == 0) {
        if (tid == 0)  out[b0] = (float)cnt;
        if (tid == 32) out[b1] = (float)cnt;
        if (have_h) {
            const int pf = tmax % 3;
#pragma unroll
            for (int k = 0; k < 4; ++k) {
                int j = tid * 4 + k;            // 0..1023
                int b = j >> 9, jj = j & 511;
                out[BB + (size_t)(b0 + b) * HH + jj] = hbuf[pf][b][(jj >> 6) * 68 + (jj & 63)];
            }
        }
    }
}

// ---------------------------------------------------------------------------
// launch
// ---------------------------------------------------------------------------
extern "C" void kernel_launch(void* const* d_in, const int* in_sizes, int n_in,
                              void* d_out, int out_size) {
    const float* x     = (const float*)d_in[0];
    const int* lengths = (const int*)d_in[1];
    const float* W_ih  = (const float*)d_in[2];
    const float* W_hh  = (const float*)d_in[3];
    const float* b_ih  = (const float*)d_in[4];
    const float* b_hh  = (const float*)d_in[5];
    const float* W1    = (const float*)d_in[6];
    const float* b1    = (const float*)d_in[7];
    const float* W2    = (const float*)d_in[8];
    const float* b2    = (const float*)d_in[9];
    float* out = (float*)d_out;

    vc_kernel<<<1, 512>>>(W1, b1, W2, b2);

    dim3 ggrid(HH / 64, (BB * TT) / 64);   // (8, 1024)
    pre_gemm<<<ggrid, 256>>>(x, W_ih, b_ih, b_hh);

    rnn_kernel<<<128, 256>>>(lengths, W_hh, out, out_size);
}